// round 5
// baseline (speedup 1.0000x reference)
#include <cuda_runtime.h>
#include <cstdint>

// Problem dims
constexpr int B_ = 8;
constexpr int H_ = 9;
constexpr int E_ = 128;
constexpr int S_ = 1025;
constexpr long long QKV_ELEMS = (long long)B_ * H_ * S_ * E_;   // 9,446,400
constexpr long long O_ELEMS   = (long long)B_ * S_ * H_ * E_;   // 9,446,400

// Scratch (device globals: allocation-free per harness rules)
__device__ float g_q[QKV_ELEMS];
__device__ float g_k[QKV_ELEMS];
__device__ float g_v[QKV_ELEMS];
__device__ float g_o[O_ELEMS];

// ---------------------------------------------------------------------------
// cp.async helpers
// ---------------------------------------------------------------------------
__device__ __forceinline__ void cp_async4(uint32_t dst, const float* src, bool p) {
    int sz = p ? 4 : 0;
    asm volatile("cp.async.ca.shared.global [%0], [%1], 4, %2;\n"
                 :: "r"(dst), "l"(src), "r"(sz));
}
__device__ __forceinline__ void cp_commit() {
    asm volatile("cp.async.commit_group;\n" ::: "memory");
}
template <int N>
__device__ __forceinline__ void cp_wait() {
    asm volatile("cp.async.wait_group %0;\n" :: "n"(N) : "memory");
}

// ---------------------------------------------------------------------------
// tf32 helpers
// ---------------------------------------------------------------------------
__device__ __forceinline__ uint32_t f2tf32(float x) {
    uint32_t r;
    asm("cvt.rna.tf32.f32 %0, %1;" : "=r"(r) : "f"(x));
    return r;
}
__device__ __forceinline__ float tf32f(float x) {
    return __uint_as_float(f2tf32(x));
}
__device__ __forceinline__ void mma8(float* c,
    uint32_t a0, uint32_t a1, uint32_t a2, uint32_t a3,
    uint32_t b0, uint32_t b1)
{
    asm volatile(
        "mma.sync.aligned.m16n8k8.row.col.f32.tf32.tf32.f32 "
        "{%0,%1,%2,%3},{%4,%5,%6,%7},{%8,%9},{%0,%1,%2,%3};"
        : "+f"(c[0]), "+f"(c[1]), "+f"(c[2]), "+f"(c[3])
        : "r"(a0), "r"(a1), "r"(a2), "r"(a3), "r"(b0), "r"(b1));
}

// ---------------------------------------------------------------------------
// Fragment-major staging offset (floats) within a 128(outer) x 16(k) tile.
// Tile = 16 blocks of 128 floats. Block id = (outer>>4)*2 + (k>>3).
// Within a block: lane = 4*(outer&7) + (k&3) (== warp laneid at read time),
// slot = ((outer>>3)&1) | (((k>>2)&1)<<1)  -> matches mma A-reg order a0..a3.
// Warp fragment read = one LDS.128 over 512 contiguous bytes (conflict-free).
// ---------------------------------------------------------------------------
__device__ __forceinline__ int stage_off(int outer, int k) {
    return (((outer >> 4) * 2 + (k >> 3)) * 128)
         + (((outer & 7) * 4 + (k & 3)) * 4)
         + (((outer >> 3) & 1) | (((k >> 2) & 1) << 1));
}

// ---------------------------------------------------------------------------
// Tensor-core GEMM tile: C[M,N] = scale * A[M,K]*B[K,N] (+bias[n]).
// Arbitrary element strides; X_KC true iff that operand's K-stride is 1.
// BM=BN=128, BK=16, 256 threads = 8 warps (4m x 2n), warp tile 32x64.
// tf32 m16n8k8; SPLIT => 3xTF32 (~fp32 accuracy).
// Pipeline: cp.async raw (single buffer) -> convert pass writes tf32 hi(/lo)
// fragment-major tiles (double buffered) -> mma loop is pure LDS.128 + HMMA.
// Dynamic smem: raw 16KB | convHi 2x16KB | (SPLIT) convLo 2x16KB.
// ---------------------------------------------------------------------------
template<bool A_KC, bool B_KC, bool SPLIT>
__device__ __forceinline__ void mma_gemm(
    const float* __restrict__ A, long long a_m, long long a_k,
    const float* __restrict__ Bp, long long b_n, long long b_k,
    float* __restrict__ C, long long c_m, long long c_n,
    int M, int N, int K, float scale, const float* __restrict__ bias)
{
    constexpr int BM = 128, BN = 128, BK = 16;
    extern __shared__ float dsm[];
    float* raw = dsm;              // [0, 4096): A tile 2048 | B tile 2048 (raw f32)
    float* cvh = dsm + 4096;       // [4096, 12288): 2 stages x (A 2048 | B 2048) hi
    float* cvl = dsm + 12288;      // split only: 2 stages x 4096 lo

    const int tid  = threadIdx.x;
    const int lane = tid & 31;
    const int wid  = tid >> 5;
    const int g    = lane >> 2;   // 0..7
    const int tg   = lane & 3;    // 0..3
    const int wm   = (wid & 3) * 32;
    const int wn   = (wid >> 2) * 64;
    const int m0   = blockIdx.x * BM;
    const int n0   = blockIdx.y * BN;

    const uint32_t raw_base = (uint32_t)__cvta_generic_to_shared(raw);

    auto load_tile_raw = [&](int kt) {
        const int k0 = kt * BK;
#pragma unroll
        for (int c = 0; c < (BM * BK) / 256; ++c) {
            int li = c * 256 + tid;
            int m, k;
            if (A_KC) { k = li & 15;  m = li >> 4; }
            else      { m = li & 127; k = li >> 7; }
            int gm = m0 + m, gk = k0 + k;
            bool p = (gm < M) && (gk < K);
            const float* src = p ? (A + (long long)gm * a_m + (long long)gk * a_k) : A;
            cp_async4(raw_base + (uint32_t)(stage_off(m, k) * 4), src, p);
        }
#pragma unroll
        for (int c = 0; c < (BN * BK) / 256; ++c) {
            int li = c * 256 + tid;
            int n, k;
            if (B_KC) { k = li & 15;  n = li >> 4; }
            else      { n = li & 127; k = li >> 7; }
            int gn = n0 + n, gk = k0 + k;
            bool p = (gn < N) && (gk < K);
            const float* src = p ? (Bp + (long long)gn * b_n + (long long)gk * b_k) : Bp;
            cp_async4(raw_base + (uint32_t)((2048 + stage_off(n, k)) * 4), src, p);
        }
    };

    float acc[2][8][4];
#pragma unroll
    for (int i = 0; i < 2; ++i)
#pragma unroll
        for (int j = 0; j < 8; ++j)
#pragma unroll
            for (int r = 0; r < 4; ++r) acc[i][j][r] = 0.0f;

    const int ktiles = (K + BK - 1) / BK;

    load_tile_raw(0);
    cp_commit();

    int buf = 0;
    for (int kt = 0; kt < ktiles; ++kt) {
        cp_wait<0>();
        __syncthreads();               // raw(kt) visible to all

        // ---- convert pass: raw -> fragment tiles (tf32 hi / lo) ----
        {
            float4* rp = reinterpret_cast<float4*>(raw);
            float4* hp = reinterpret_cast<float4*>(cvh + buf * 4096);
            float4* lp = reinterpret_cast<float4*>(cvl + buf * 4096);
#pragma unroll
            for (int it = 0; it < 4; ++it) {
                int f = it * 256 + tid;          // 1024 float4 = whole 4096 floats
                float4 x = rp[f];
                float4 h;
                h.x = tf32f(x.x); h.y = tf32f(x.y);
                h.z = tf32f(x.z); h.w = tf32f(x.w);
                hp[f] = h;
                if (SPLIT) {
                    float4 l;
                    l.x = tf32f(x.x - h.x); l.y = tf32f(x.y - h.y);
                    l.z = tf32f(x.z - h.z); l.w = tf32f(x.w - h.w);
                    lp[f] = l;
                }
            }
        }
        __syncthreads();               // conv(kt) ready; raw free for reuse

        if (kt + 1 < ktiles) { load_tile_raw(kt + 1); cp_commit(); }

        // ---- mma on converted tiles ----
        const float* Ah_t = cvh + buf * 4096;
        const float* Bh_t = Ah_t + 2048;
        const float* Al_t = cvl + buf * 4096;
        const float* Bl_t = Al_t + 2048;
        const int lo16 = lane * 4;     // float offset of this lane within a block

#pragma unroll
        for (int ks = 0; ks < 2; ++ks) {
            float4 fa[2], fal[2];
#pragma unroll
            for (int mf = 0; mf < 2; ++mf) {
                const int fb = (((wm >> 4) + mf) * 2 + ks) * 128 + lo16;
                fa[mf] = *reinterpret_cast<const float4*>(Ah_t + fb);
                if (SPLIT) fal[mf] = *reinterpret_cast<const float4*>(Al_t + fb);
            }
#pragma unroll
            for (int p = 0; p < 4; ++p) {
                const int fb = (((wn >> 4) + p) * 2 + ks) * 128 + lo16;
                float4 bh = *reinterpret_cast<const float4*>(Bh_t + fb);
                float4 bl;
                if (SPLIT) bl = *reinterpret_cast<const float4*>(Bl_t + fb);
#pragma unroll
                for (int mf = 0; mf < 2; ++mf) {
                    uint32_t a0 = __float_as_uint(fa[mf].x), a1 = __float_as_uint(fa[mf].y);
                    uint32_t a2 = __float_as_uint(fa[mf].z), a3 = __float_as_uint(fa[mf].w);
                    // j even: B regs (x, z); j odd: (y, w)
                    float* ce = acc[mf][2 * p];
                    float* co = acc[mf][2 * p + 1];
                    if (SPLIT) {
                        uint32_t l0 = __float_as_uint(fal[mf].x), l1 = __float_as_uint(fal[mf].y);
                        uint32_t l2 = __float_as_uint(fal[mf].z), l3 = __float_as_uint(fal[mf].w);
                        mma8(ce, a0, a1, a2, a3, __float_as_uint(bl.x), __float_as_uint(bl.z));
                        mma8(ce, l0, l1, l2, l3, __float_as_uint(bh.x), __float_as_uint(bh.z));
                        mma8(co, a0, a1, a2, a3, __float_as_uint(bl.y), __float_as_uint(bl.w));
                        mma8(co, l0, l1, l2, l3, __float_as_uint(bh.y), __float_as_uint(bh.w));
                    }
                    mma8(ce, a0, a1, a2, a3, __float_as_uint(bh.x), __float_as_uint(bh.z));
                    mma8(co, a0, a1, a2, a3, __float_as_uint(bh.y), __float_as_uint(bh.w));
                }
            }
        }
        buf ^= 1;
    }

    // ---- epilogue ----
#pragma unroll
    for (int mf = 0; mf < 2; ++mf) {
#pragma unroll
        for (int nf = 0; nf < 8; ++nf) {
            const int r0 = m0 + wm + mf * 16 + g;
            const int r1 = r0 + 8;
            const int cb = n0 + wn + nf * 8 + 2 * tg;
            float v0 = acc[mf][nf][0] * scale;
            float v1 = acc[mf][nf][1] * scale;
            float v2 = acc[mf][nf][2] * scale;
            float v3 = acc[mf][nf][3] * scale;
            if (bias) {
                if (cb < N)     { v0 += bias[cb];     v2 += bias[cb]; }
                if (cb + 1 < N) { v1 += bias[cb + 1]; v3 += bias[cb + 1]; }
            }
            if (r0 < M) {
                if (cb < N)     C[(long long)r0 * c_m + (long long)cb * c_n] = v0;
                if (cb + 1 < N) C[(long long)r0 * c_m + (long long)(cb + 1) * c_n] = v1;
            }
            if (r1 < M) {
                if (cb < N)     C[(long long)r1 * c_m + (long long)cb * c_n] = v2;
                if (cb + 1 < N) C[(long long)r1 * c_m + (long long)(cb + 1) * c_n] = v3;
            }
        }
    }
}

// Dynamic smem sizes (bytes)
constexpr int SMEM_SINGLE = 12288 * 4;  // 48 KB
constexpr int SMEM_SPLIT  = 20480 * 4;  // 80 KB

// ---------------------------------------------------------------------------
// Stage 1: q/k/v[b,h,s,f] = sum_e x[b,e,s] * {Q,K,V}[h,e,f]   (3xTF32)
// ---------------------------------------------------------------------------
__global__ __launch_bounds__(256, 2) void qkv_kernel(
    const float* __restrict__ x, const float* __restrict__ Qm,
    const float* __restrict__ Km, const float* __restrict__ Vm)
{
    const int z  = blockIdx.z;
    const int bh = z % (B_ * H_);
    const int p  = z / (B_ * H_);
    const int b  = bh / H_;
    const int h  = bh % H_;
    const float* A  = x + (long long)b * E_ * S_;           // A[m=s][k=e]: +k*S+m
    const float* Bp = (p == 0 ? Qm : (p == 1 ? Km : Vm)) + (long long)h * E_ * E_;
    float* C = (p == 0 ? g_q : (p == 1 ? g_k : g_v)) + (long long)bh * S_ * E_;
    mma_gemm<false, false, true>(A, 1, S_,
                                 Bp, 1, E_,
                                 C, E_, 1,
                                 S_, E_, E_, 1.0f, nullptr);
}

// ---------------------------------------------------------------------------
// Stage 2: raw scores into atten region: cor[s,t] = (q[s]·k[t]) / sqrt(E)  (3xTF32)
// ---------------------------------------------------------------------------
__global__ __launch_bounds__(256, 2) void scores_kernel(float* __restrict__ att)
{
    const int bh = blockIdx.z;
    const float* A  = g_q + (long long)bh * S_ * E_;
    const float* Bp = g_k + (long long)bh * S_ * E_;
    float* C = att + (long long)bh * S_ * S_;
    mma_gemm<true, true, true>(A, E_, 1,
                               Bp, E_, 1,
                               C, S_, 1,
                               S_, S_, E_, 0.08838834764831845f, nullptr);
}

// ---------------------------------------------------------------------------
// Stage 3: in-place row softmax over length S=1025. One 256-thread block/row.
// ---------------------------------------------------------------------------
__global__ __launch_bounds__(256) void softmax_kernel(float* __restrict__ att)
{
    const long long row = blockIdx.x;
    float* p = att + row * (long long)S_;
    const int tid = threadIdx.x;

    float v[5];
    float mx = -3.4e38f;
#pragma unroll
    for (int i = 0; i < 5; ++i) {
        int idx = tid + i * 256;
        v[i] = (idx < S_) ? p[idx] : -3.4e38f;
        mx = fmaxf(mx, v[i]);
    }
    __shared__ float redm[8];
    __shared__ float reds[8];
#pragma unroll
    for (int o = 16; o > 0; o >>= 1) mx = fmaxf(mx, __shfl_xor_sync(0xffffffffu, mx, o));
    if ((tid & 31) == 0) redm[tid >> 5] = mx;
    __syncthreads();
    mx = redm[0];
#pragma unroll
    for (int w = 1; w < 8; ++w) mx = fmaxf(mx, redm[w]);

    float sum = 0.0f;
#pragma unroll
    for (int i = 0; i < 5; ++i) {
        int idx = tid + i * 256;
        if (idx < S_) { v[i] = __expf(v[i] - mx); sum += v[i]; }
        else v[i] = 0.0f;
    }
#pragma unroll
    for (int o = 16; o > 0; o >>= 1) sum += __shfl_xor_sync(0xffffffffu, sum, o);
    if ((tid & 31) == 0) reds[tid >> 5] = sum;
    __syncthreads();
    sum = reds[0];
#pragma unroll
    for (int w = 1; w < 8; ++w) sum += reds[w];
    const float inv = __frcp_rn(sum);

#pragma unroll
    for (int i = 0; i < 5; ++i) {
        int idx = tid + i * 256;
        if (idx < S_) p[idx] = v[i] * inv;
    }
}

// ---------------------------------------------------------------------------
// Stage 4: o[b,s,h*E+f] = sum_t atten[b,h,s,t] * v[b,h,t,f]   (single tf32)
// ---------------------------------------------------------------------------
__global__ __launch_bounds__(256, 2) void av_kernel(const float* __restrict__ att)
{
    const int bh = blockIdx.z;
    const int b = bh / H_;
    const int h = bh % H_;
    const float* A  = att + (long long)bh * S_ * S_;
    const float* Bp = g_v + (long long)bh * S_ * E_;
    float* C = g_o + (long long)b * S_ * (H_ * E_) + (long long)h * E_;
    mma_gemm<true, false, false>(A, S_, 1,
                                 Bp, 1, E_,
                                 C, (long long)(H_ * E_), 1,
                                 S_, E_, S_, 1.0f, nullptr);
}

// ---------------------------------------------------------------------------
// Stage 5: out[b,e,s] = sum_k o[b,s,k] * W[e,k] + bias[e]   (single tf32)
// ---------------------------------------------------------------------------
__global__ __launch_bounds__(256, 2) void proj_kernel(
    const float* __restrict__ W, const float* __restrict__ bias,
    float* __restrict__ out)
{
    const int b = blockIdx.z;
    const float* A = g_o + (long long)b * S_ * (H_ * E_);
    float* C = out + (long long)b * E_ * S_;
    mma_gemm<true, true, false>(A, (long long)(H_ * E_), 1,
                                W, (long long)(H_ * E_), 1,
                                C, 1, S_,
                                S_, E_, H_ * E_, 1.0f, bias);
}

// ---------------------------------------------------------------------------
extern "C" void kernel_launch(void* const* d_in, const int* in_sizes, int n_in,
                              void* d_out, int out_size)
{
    (void)in_sizes; (void)n_in; (void)out_size;
    const float* x    = (const float*)d_in[0];
    const float* Qm   = (const float*)d_in[1];
    const float* Km   = (const float*)d_in[2];
    const float* Vm   = (const float*)d_in[3];
    const float* W    = (const float*)d_in[4];
    const float* bias = (const float*)d_in[5];

    float* out = (float*)d_out;
    float* att = out + (long long)B_ * E_ * S_;   // atten region follows out

    const int MT = (S_ + 127) / 128;  // 9

    // Opt-in to >48KB dynamic smem for the split kernels (host-side attribute;
    // not a stream op, executes identically during and outside graph capture).
    static bool attr_done = false;
    if (!attr_done) {
        cudaFuncSetAttribute(qkv_kernel,
            cudaFuncAttributeMaxDynamicSharedMemorySize, SMEM_SPLIT);
        cudaFuncSetAttribute(scores_kernel,
            cudaFuncAttributeMaxDynamicSharedMemorySize, SMEM_SPLIT);
        cudaFuncSetAttribute(av_kernel,
            cudaFuncAttributeMaxDynamicSharedMemorySize, SMEM_SINGLE);
        cudaFuncSetAttribute(proj_kernel,
            cudaFuncAttributeMaxDynamicSharedMemorySize, SMEM_SINGLE);
        attr_done = true;
    }

    qkv_kernel    <<<dim3(MT, 1, B_ * H_ * 3), 256, SMEM_SPLIT>>>(x, Qm, Km, Vm);
    scores_kernel <<<dim3(MT, MT, B_ * H_),    256, SMEM_SPLIT>>>(att);
    softmax_kernel<<<dim3(B_ * H_ * S_),       256>>>(att);
    av_kernel     <<<dim3(MT, 1, B_ * H_),     256, SMEM_SINGLE>>>(att);
    proj_kernel   <<<dim3(MT, 1, B_),          256, SMEM_SINGLE>>>(W, bias, out);
}

// round 6
// speedup vs baseline: 1.0811x; 1.0811x over previous
#include <cuda_runtime.h>
#include <cstdint>

// Problem dims
constexpr int B_ = 8;
constexpr int H_ = 9;
constexpr int E_ = 128;
constexpr int S_ = 1025;
constexpr long long QKV_ELEMS = (long long)B_ * H_ * S_ * E_;   // 9,446,400
constexpr long long O_ELEMS   = (long long)B_ * S_ * H_ * E_;   // 9,446,400

// Scratch (device globals: allocation-free per harness rules)
__device__ float g_q[QKV_ELEMS];
__device__ float g_k[QKV_ELEMS];
__device__ float g_v[QKV_ELEMS];
__device__ float g_o[O_ELEMS];

// ---------------------------------------------------------------------------
// cp.async helpers
// ---------------------------------------------------------------------------
__device__ __forceinline__ void cp_async4(uint32_t dst, const float* src, bool p) {
    int sz = p ? 4 : 0;
    asm volatile("cp.async.ca.shared.global [%0], [%1], 4, %2;\n"
                 :: "r"(dst), "l"(src), "r"(sz));
}
__device__ __forceinline__ void cp_commit() {
    asm volatile("cp.async.commit_group;\n" ::: "memory");
}
template <int N>
__device__ __forceinline__ void cp_wait() {
    asm volatile("cp.async.wait_group %0;\n" :: "n"(N) : "memory");
}

// ---------------------------------------------------------------------------
// tf32 helpers
// ---------------------------------------------------------------------------
__device__ __forceinline__ uint32_t f2tf32(float x) {
    uint32_t r;
    asm("cvt.rna.tf32.f32 %0, %1;" : "=r"(r) : "f"(x));
    return r;
}
__device__ __forceinline__ void mma8(float* c,
    uint32_t a0, uint32_t a1, uint32_t a2, uint32_t a3,
    uint32_t b0, uint32_t b1)
{
    asm volatile(
        "mma.sync.aligned.m16n8k8.row.col.f32.tf32.tf32.f32 "
        "{%0,%1,%2,%3},{%4,%5,%6,%7},{%8,%9},{%0,%1,%2,%3};"
        : "+f"(c[0]), "+f"(c[1]), "+f"(c[2]), "+f"(c[3])
        : "r"(a0), "r"(a1), "r"(a2), "r"(a3), "r"(b0), "r"(b1));
}

// ---------------------------------------------------------------------------
// Fragment-major staging offset (floats) within a 128(outer) x 16(k) tile.
// Tile = 16 blocks of 128 floats. Block id = (outer>>4)*2 + (k>>3).
// Within a block: lane = 4*(outer&7) + (k&3) (== warp laneid at read time),
// slot = ((outer>>3)&1) | (((k>>2)&1)<<1)  -> matches mma A-reg order a0..a3
// (and for B gives regs for two adjacent n-tiles as x/z and y/w).
// Warp fragment read = one LDS.128 over 512 contiguous bytes (conflict-free).
// Verified bit-correct in R5 (rel_err identical to R4's scalar layout).
// ---------------------------------------------------------------------------
__device__ __forceinline__ int stage_off(int outer, int k) {
    return (((outer >> 4) * 2 + (k >> 3)) * 128)
         + (((outer & 7) * 4 + (k & 3)) * 4)
         + (((outer >> 3) & 1) | (((k >> 2) & 1) << 1));
}

// ---------------------------------------------------------------------------
// Tensor-core GEMM tile: C[M,N] = scale * A[M,K]*B[K,N] (+bias[n]).
// Arbitrary element strides; X_KC true iff that operand's K-stride is 1.
// BM=BN=128, BK=16, 256 threads = 8 warps (4m x 2n), warp tile 32x64.
// tf32 m16n8k8; SPLIT => 3xTF32 (~fp32 accuracy).
// R4 pipeline (double-buffered raw cp.async, cp_wait<1>) + R5 fragment-major
// layout; tf32 conversion in registers right after LDS.128 (no smem pass).
// Static smem: 2 stages x (A 2048 + B 2048 floats) = 32 KB.
// ---------------------------------------------------------------------------
template<bool A_KC, bool B_KC, bool SPLIT>
__device__ __forceinline__ void mma_gemm(
    const float* __restrict__ A, long long a_m, long long a_k,
    const float* __restrict__ Bp, long long b_n, long long b_k,
    float* __restrict__ C, long long c_m, long long c_n,
    int M, int N, int K, float scale, const float* __restrict__ bias)
{
    constexpr int BM = 128, BN = 128, BK = 16;
    __shared__ float sraw[2 * 4096];   // [stage][A 2048 | B 2048]

    const int tid  = threadIdx.x;
    const int lane = tid & 31;
    const int wid  = tid >> 5;
    const int g    = lane >> 2;   // 0..7
    const int tg   = lane & 3;    // 0..3
    const int wm   = (wid & 3) * 32;
    const int wn   = (wid >> 2) * 64;
    const int m0   = blockIdx.x * BM;
    const int n0   = blockIdx.y * BN;

    const uint32_t raw_base = (uint32_t)__cvta_generic_to_shared(sraw);

    auto load_tile = [&](int kt, int stage) {
        const int k0 = kt * BK;
        const uint32_t sb = raw_base + (uint32_t)(stage * 4096 * 4);
#pragma unroll
        for (int c = 0; c < (BM * BK) / 256; ++c) {
            int li = c * 256 + tid;
            int m, k;
            if (A_KC) { k = li & 15;  m = li >> 4; }
            else      { m = li & 127; k = li >> 7; }
            int gm = m0 + m, gk = k0 + k;
            bool p = (gm < M) && (gk < K);
            const float* src = p ? (A + (long long)gm * a_m + (long long)gk * a_k) : A;
            cp_async4(sb + (uint32_t)(stage_off(m, k) * 4), src, p);
        }
#pragma unroll
        for (int c = 0; c < (BN * BK) / 256; ++c) {
            int li = c * 256 + tid;
            int n, k;
            if (B_KC) { k = li & 15;  n = li >> 4; }
            else      { n = li & 127; k = li >> 7; }
            int gn = n0 + n, gk = k0 + k;
            bool p = (gn < N) && (gk < K);
            const float* src = p ? (Bp + (long long)gn * b_n + (long long)gk * b_k) : Bp;
            cp_async4(sb + (uint32_t)((2048 + stage_off(n, k)) * 4), src, p);
        }
    };

    float acc[2][8][4];
#pragma unroll
    for (int i = 0; i < 2; ++i)
#pragma unroll
        for (int j = 0; j < 8; ++j)
#pragma unroll
            for (int r = 0; r < 4; ++r) acc[i][j][r] = 0.0f;

    const int ktiles = (K + BK - 1) / BK;

    load_tile(0, 0);
    cp_commit();

    const int lo16 = lane * 4;         // lane's float offset within a 128-float block

    int buf = 0;
    for (int kt = 0; kt < ktiles; ++kt) {
        if (kt + 1 < ktiles) load_tile(kt + 1, buf ^ 1);
        cp_commit();
        cp_wait<1>();
        __syncthreads();

        const float* At = sraw + buf * 4096;
        const float* Bt = At + 2048;

#pragma unroll
        for (int ks = 0; ks < 2; ++ks) {
            // ---- A fragments: 2 LDS.128, convert in regs ----
            uint32_t Ah[2][4], Al[2][4];
#pragma unroll
            for (int mf = 0; mf < 2; ++mf) {
                const int fb = (((wm >> 4) + mf) * 2 + ks) * 128 + lo16;
                float4 x = *reinterpret_cast<const float4*>(At + fb);
                Ah[mf][0] = f2tf32(x.x); Ah[mf][1] = f2tf32(x.y);
                Ah[mf][2] = f2tf32(x.z); Ah[mf][3] = f2tf32(x.w);
                if (SPLIT) {
                    Al[mf][0] = f2tf32(x.x - __uint_as_float(Ah[mf][0]));
                    Al[mf][1] = f2tf32(x.y - __uint_as_float(Ah[mf][1]));
                    Al[mf][2] = f2tf32(x.z - __uint_as_float(Ah[mf][2]));
                    Al[mf][3] = f2tf32(x.w - __uint_as_float(Ah[mf][3]));
                }
            }
            // ---- B fragments: 4 LDS.128, each feeds two n-tiles ----
#pragma unroll
            for (int p = 0; p < 4; ++p) {
                const int fb = (((wn >> 4) + p) * 2 + ks) * 128 + lo16;
                float4 x = *reinterpret_cast<const float4*>(Bt + fb);
                uint32_t bhx = f2tf32(x.x), bhy = f2tf32(x.y);
                uint32_t bhz = f2tf32(x.z), bhw = f2tf32(x.w);
                uint32_t blx, bly, blz, blw;
                if (SPLIT) {
                    blx = f2tf32(x.x - __uint_as_float(bhx));
                    bly = f2tf32(x.y - __uint_as_float(bhy));
                    blz = f2tf32(x.z - __uint_as_float(bhz));
                    blw = f2tf32(x.w - __uint_as_float(bhw));
                }
#pragma unroll
                for (int mf = 0; mf < 2; ++mf) {
                    float* ce = acc[mf][2 * p];      // even n-tile: regs (x,z)
                    float* co = acc[mf][2 * p + 1];  // odd  n-tile: regs (y,w)
                    if (SPLIT) {
                        mma8(ce, Ah[mf][0], Ah[mf][1], Ah[mf][2], Ah[mf][3], blx, blz);
                        mma8(ce, Al[mf][0], Al[mf][1], Al[mf][2], Al[mf][3], bhx, bhz);
                        mma8(co, Ah[mf][0], Ah[mf][1], Ah[mf][2], Ah[mf][3], bly, blw);
                        mma8(co, Al[mf][0], Al[mf][1], Al[mf][2], Al[mf][3], bhy, bhw);
                    }
                    mma8(ce, Ah[mf][0], Ah[mf][1], Ah[mf][2], Ah[mf][3], bhx, bhz);
                    mma8(co, Ah[mf][0], Ah[mf][1], Ah[mf][2], Ah[mf][3], bhy, bhw);
                }
            }
        }
        __syncthreads();               // protect buf before next cp.async overwrite
        buf ^= 1;
    }

    // ---- epilogue ----
#pragma unroll
    for (int mf = 0; mf < 2; ++mf) {
#pragma unroll
        for (int nf = 0; nf < 8; ++nf) {
            const int r0 = m0 + wm + mf * 16 + g;
            const int r1 = r0 + 8;
            const int cb = n0 + wn + nf * 8 + 2 * tg;
            float v0 = acc[mf][nf][0] * scale;
            float v1 = acc[mf][nf][1] * scale;
            float v2 = acc[mf][nf][2] * scale;
            float v3 = acc[mf][nf][3] * scale;
            if (bias) {
                if (cb < N)     { v0 += bias[cb];     v2 += bias[cb]; }
                if (cb + 1 < N) { v1 += bias[cb + 1]; v3 += bias[cb + 1]; }
            }
            if (r0 < M) {
                if (cb < N)     C[(long long)r0 * c_m + (long long)cb * c_n] = v0;
                if (cb + 1 < N) C[(long long)r0 * c_m + (long long)(cb + 1) * c_n] = v1;
            }
            if (r1 < M) {
                if (cb < N)     C[(long long)r1 * c_m + (long long)cb * c_n] = v2;
                if (cb + 1 < N) C[(long long)r1 * c_m + (long long)(cb + 1) * c_n] = v3;
            }
        }
    }
}

// ---------------------------------------------------------------------------
// Stage 1: q/k/v[b,h,s,f] = sum_e x[b,e,s] * {Q,K,V}[h,e,f]   (3xTF32)
// ---------------------------------------------------------------------------
__global__ __launch_bounds__(256, 2) void qkv_kernel(
    const float* __restrict__ x, const float* __restrict__ Qm,
    const float* __restrict__ Km, const float* __restrict__ Vm)
{
    const int z  = blockIdx.z;
    const int bh = z % (B_ * H_);
    const int p  = z / (B_ * H_);
    const int b  = bh / H_;
    const int h  = bh % H_;
    const float* A  = x + (long long)b * E_ * S_;           // A[m=s][k=e]: +k*S+m
    const float* Bp = (p == 0 ? Qm : (p == 1 ? Km : Vm)) + (long long)h * E_ * E_;
    float* C = (p == 0 ? g_q : (p == 1 ? g_k : g_v)) + (long long)bh * S_ * E_;
    mma_gemm<false, false, true>(A, 1, S_,
                                 Bp, 1, E_,
                                 C, E_, 1,
                                 S_, E_, E_, 1.0f, nullptr);
}

// ---------------------------------------------------------------------------
// Stage 2: raw scores into atten region: cor[s,t] = (q[s]·k[t]) / sqrt(E)  (3xTF32)
// ---------------------------------------------------------------------------
__global__ __launch_bounds__(256, 2) void scores_kernel(float* __restrict__ att)
{
    const int bh = blockIdx.z;
    const float* A  = g_q + (long long)bh * S_ * E_;
    const float* Bp = g_k + (long long)bh * S_ * E_;
    float* C = att + (long long)bh * S_ * S_;
    mma_gemm<true, true, true>(A, E_, 1,
                               Bp, E_, 1,
                               C, S_, 1,
                               S_, S_, E_, 0.08838834764831845f, nullptr);
}

// ---------------------------------------------------------------------------
// Stage 3: in-place row softmax over length S=1025. One 256-thread block/row.
// ---------------------------------------------------------------------------
__global__ __launch_bounds__(256) void softmax_kernel(float* __restrict__ att)
{
    const long long row = blockIdx.x;
    float* p = att + row * (long long)S_;
    const int tid = threadIdx.x;

    float v[5];
    float mx = -3.4e38f;
#pragma unroll
    for (int i = 0; i < 5; ++i) {
        int idx = tid + i * 256;
        v[i] = (idx < S_) ? p[idx] : -3.4e38f;
        mx = fmaxf(mx, v[i]);
    }
    __shared__ float redm[8];
    __shared__ float reds[8];
#pragma unroll
    for (int o = 16; o > 0; o >>= 1) mx = fmaxf(mx, __shfl_xor_sync(0xffffffffu, mx, o));
    if ((tid & 31) == 0) redm[tid >> 5] = mx;
    __syncthreads();
    mx = redm[0];
#pragma unroll
    for (int w = 1; w < 8; ++w) mx = fmaxf(mx, redm[w]);

    float sum = 0.0f;
#pragma unroll
    for (int i = 0; i < 5; ++i) {
        int idx = tid + i * 256;
        if (idx < S_) { v[i] = __expf(v[i] - mx); sum += v[i]; }
        else v[i] = 0.0f;
    }
#pragma unroll
    for (int o = 16; o > 0; o >>= 1) sum += __shfl_xor_sync(0xffffffffu, sum, o);
    if ((tid & 31) == 0) reds[tid >> 5] = sum;
    __syncthreads();
    sum = reds[0];
#pragma unroll
    for (int w = 1; w < 8; ++w) sum += reds[w];
    const float inv = __frcp_rn(sum);

#pragma unroll
    for (int i = 0; i < 5; ++i) {
        int idx = tid + i * 256;
        if (idx < S_) p[idx] = v[i] * inv;
    }
}

// ---------------------------------------------------------------------------
// Stage 4: o[b,s,h*E+f] = sum_t atten[b,h,s,t] * v[b,h,t,f]   (single tf32)
// ---------------------------------------------------------------------------
__global__ __launch_bounds__(256, 2) void av_kernel(const float* __restrict__ att)
{
    const int bh = blockIdx.z;
    const int b = bh / H_;
    const int h = bh % H_;
    const float* A  = att + (long long)bh * S_ * S_;
    const float* Bp = g_v + (long long)bh * S_ * E_;
    float* C = g_o + (long long)b * S_ * (H_ * E_) + (long long)h * E_;
    mma_gemm<true, false, false>(A, S_, 1,
                                 Bp, 1, E_,
                                 C, (long long)(H_ * E_), 1,
                                 S_, E_, S_, 1.0f, nullptr);
}

// ---------------------------------------------------------------------------
// Stage 5: out[b,e,s] = sum_k o[b,s,k] * W[e,k] + bias[e]   (single tf32)
// ---------------------------------------------------------------------------
__global__ __launch_bounds__(256, 2) void proj_kernel(
    const float* __restrict__ W, const float* __restrict__ bias,
    float* __restrict__ out)
{
    const int b = blockIdx.z;
    const float* A = g_o + (long long)b * S_ * (H_ * E_);
    float* C = out + (long long)b * E_ * S_;
    mma_gemm<true, true, false>(A, (long long)(H_ * E_), 1,
                                W, (long long)(H_ * E_), 1,
                                C, 1, S_,
                                S_, E_, H_ * E_, 1.0f, bias);
}

// ---------------------------------------------------------------------------
extern "C" void kernel_launch(void* const* d_in, const int* in_sizes, int n_in,
                              void* d_out, int out_size)
{
    (void)in_sizes; (void)n_in; (void)out_size;
    const float* x    = (const float*)d_in[0];
    const float* Qm   = (const float*)d_in[1];
    const float* Km   = (const float*)d_in[2];
    const float* Vm   = (const float*)d_in[3];
    const float* W    = (const float*)d_in[4];
    const float* bias = (const float*)d_in[5];

    float* out = (float*)d_out;
    float* att = out + (long long)B_ * E_ * S_;   // atten region follows out

    const int MT = (S_ + 127) / 128;  // 9

    qkv_kernel    <<<dim3(MT, 1, B_ * H_ * 3), 256>>>(x, Qm, Km, Vm);
    scores_kernel <<<dim3(MT, MT, B_ * H_),    256>>>(att);
    softmax_kernel<<<dim3(B_ * H_ * S_),       256>>>(att);
    av_kernel     <<<dim3(MT, 1, B_ * H_),     256>>>(att);
    proj_kernel   <<<dim3(MT, 1, B_),          256>>>(W, bias, out);
}

// round 7
// speedup vs baseline: 1.3122x; 1.2138x over previous
#include <cuda_runtime.h>
#include <cstdint>

// Problem dims
constexpr int B_  = 8;
constexpr int H_  = 9;
constexpr int E_  = 128;
constexpr int S_  = 1025;
constexpr int HE_ = H_ * E_;            // 1152
constexpr int SP_ = 1028;               // padded S for v rows (16B-aligned, zero pad)
constexpr long long QKV_ELEMS = (long long)B_ * H_ * S_ * E_;   // 9,446,400
constexpr long long O_ELEMS   = (long long)B_ * S_ * HE_;       // 9,446,400

// Scratch (device globals: allocation-free per harness rules)
__device__ float g_xh[(long long)B_ * S_ * E_];     // x transposed [b][s][e], tf32 hi
__device__ float g_xl[(long long)B_ * S_ * E_];     // lo
__device__ float g_pth[3 * H_ * E_ * E_];           // Q/K/V transposed [p][h][f][e], hi
__device__ float g_ptl[3 * H_ * E_ * E_];           // lo
__device__ float g_wh[E_ * HE_];                    // W rounded to tf32
__device__ float g_qh[QKV_ELEMS];                   // q [bh][s][e] hi
__device__ float g_ql[QKV_ELEMS];                   // q lo
__device__ float g_kh[QKV_ELEMS];                   // k hi
__device__ float g_kl[QKV_ELEMS];                   // k lo
__device__ float g_v [(long long)B_ * H_ * E_ * SP_]; // v transposed [bh][f][t], tf32
__device__ float g_o [O_ELEMS];                     // o [b][s][h*E+f], tf32

// ---------------------------------------------------------------------------
// async-copy / tf32 / mma helpers
// ---------------------------------------------------------------------------
__device__ __forceinline__ void cp_async4(uint32_t dst, const float* src, bool p) {
    int sz = p ? 4 : 0;
    asm volatile("cp.async.ca.shared.global [%0], [%1], 4, %2;\n"
                 :: "r"(dst), "l"(src), "r"(sz));
}
__device__ __forceinline__ void cp_async16(uint32_t dst, const float* src, bool p) {
    int sz = p ? 16 : 0;
    asm volatile("cp.async.cg.shared.global [%0], [%1], 16, %2;\n"
                 :: "r"(dst), "l"(src), "r"(sz));
}
__device__ __forceinline__ void cp_commit() {
    asm volatile("cp.async.commit_group;\n" ::: "memory");
}
template <int N>
__device__ __forceinline__ void cp_wait() {
    asm volatile("cp.async.wait_group %0;\n" :: "n"(N) : "memory");
}
__device__ __forceinline__ uint32_t f2tf32(float x) {
    uint32_t r;
    asm("cvt.rna.tf32.f32 %0, %1;" : "=r"(r) : "f"(x));
    return r;
}
__device__ __forceinline__ float tf32f(float x) { return __uint_as_float(f2tf32(x)); }

__device__ __forceinline__ void mma8(float* c,
    uint32_t a0, uint32_t a1, uint32_t a2, uint32_t a3,
    uint32_t b0, uint32_t b1)
{
    asm volatile(
        "mma.sync.aligned.m16n8k8.row.col.f32.tf32.tf32.f32 "
        "{%0,%1,%2,%3},{%4,%5,%6,%7},{%8,%9},{%0,%1,%2,%3};"
        : "+f"(c[0]), "+f"(c[1]), "+f"(c[2]), "+f"(c[3])
        : "r"(a0), "r"(a1), "r"(a2), "r"(a3), "r"(b0), "r"(b1));
}
__device__ __forceinline__ void ldsm4(uint32_t addr, uint32_t r[4]) {
    asm volatile("ldmatrix.sync.aligned.m8n8.x4.shared.b16 {%0,%1,%2,%3}, [%4];"
                 : "=r"(r[0]), "=r"(r[1]), "=r"(r[2]), "=r"(r[3]) : "r"(addr));
}

// ---------------------------------------------------------------------------
// GEMM core. All operands K-contiguous: X[outer][k], gmem row stride ld.
// smem tiles [outer 128][k 16], row stride LDK=20 floats (80B: ldmatrix rows
// land on 8 distinct 4-bank groups -> conflict-free; 16B-aligned for cp16).
// 256 thr = 8 warps (4m x 2n), warp 32x64, tf32 m16n8k8 via ldmatrix.x4.
// SPLIT: A/B given as hi+lo pairs, 3 mma per fragment (3xTF32), no in-loop cvt.
// VECA/VECB: cp.async 16B (requires 16B-aligned rows; klim = allocated row len).
// CVTA: round A in regs after ldmatrix (raw fp32 operand, e.g. attention).
// EPI: 0 = C=acc*scale(+bias); 1 = hi->C, lo->C2 (tf32 split); 2 = C=tf32(acc).
// ---------------------------------------------------------------------------
constexpr int LDK    = 20;
constexpr int TILE_F = 128 * LDK;   // 2560 floats per operand tile

template<bool SPLIT, bool VECA, bool VECB, bool CVTA, int EPI>
__device__ __forceinline__ void mma_gemm(
    const float* __restrict__ Ah, const float* __restrict__ Al, long long lda, int kalim,
    const float* __restrict__ Bh, const float* __restrict__ Bl, long long ldb, int kblim,
    float* __restrict__ C, float* __restrict__ C2, long long c_m, long long c_n,
    int M, int N, int K, float scale, const float* __restrict__ bias)
{
    constexpr int STAGE = SPLIT ? 4 * TILE_F : 2 * TILE_F;
    extern __shared__ float sm[];

    const int tid  = threadIdx.x;
    const int lane = tid & 31;
    const int wid  = tid >> 5;
    const int g    = lane >> 2;
    const int tg   = lane & 3;
    const int wm   = (wid & 3) * 32;
    const int wn   = (wid >> 2) * 64;
    const int m0   = blockIdx.x * 128;
    const int n0   = blockIdx.y * 128;

    const uint32_t smb = (uint32_t)__cvta_generic_to_shared(sm);

    // one operand tile (128 outer x 16 k) into smem at byte base `dst`
    auto load_op_vec = [&](const float* src, long long ld, int klim, int o0,
                           int onum, int k0, uint32_t dst) {
#pragma unroll
        for (int it = 0; it < 2; ++it) {
            int idx = it * 256 + tid;        // 512 float4
            int o  = idx >> 2;
            int k4 = (idx & 3) * 4;
            int go = o0 + o, gk = k0 + k4;
            bool p = (go < onum) && (gk + 4 <= klim);
            const float* s = p ? (src + (long long)go * ld + gk) : src;
            cp_async16(dst + (uint32_t)((o * LDK + k4) * 4), s, p);
        }
    };
    auto load_op_sca = [&](const float* src, long long ld, int Kc, int o0,
                           int onum, int k0, uint32_t dst) {
#pragma unroll
        for (int it = 0; it < 8; ++it) {
            int idx = it * 256 + tid;        // 2048 floats
            int o = idx >> 4;
            int k = idx & 15;
            int go = o0 + o, gk = k0 + k;
            bool p = (go < onum) && (gk < Kc);
            const float* s = p ? (src + (long long)go * ld + gk) : src;
            cp_async4(dst + (uint32_t)((o * LDK + k) * 4), s, p);
        }
    };

    auto load_tile = [&](int kt, int stage) {
        const int k0 = kt * 16;
        const uint32_t sb = smb + (uint32_t)(stage * STAGE * 4);
        if (VECA) load_op_vec(Ah, lda, kalim, m0, M, k0, sb);
        else      load_op_sca(Ah, lda, K,     m0, M, k0, sb);
        if (VECB) load_op_vec(Bh, ldb, kblim, n0, N, k0, sb + TILE_F * 4);
        else      load_op_sca(Bh, ldb, K,     n0, N, k0, sb + TILE_F * 4);
        if (SPLIT) {
            load_op_vec(Al, lda, kalim, m0, M, k0, sb + 2 * TILE_F * 4);
            load_op_vec(Bl, ldb, kblim, n0, N, k0, sb + 3 * TILE_F * 4);
        }
    };

    float acc[2][8][4];
#pragma unroll
    for (int i = 0; i < 2; ++i)
#pragma unroll
        for (int j = 0; j < 8; ++j)
#pragma unroll
            for (int r = 0; r < 4; ++r) acc[i][j][r] = 0.0f;

    const int ktiles = (K + 15) / 16;
    load_tile(0, 0);
    cp_commit();

    // per-lane ldmatrix row addresses (byte offsets within an operand tile)
    // A x4: grp0 rows m0-7 @k, grp1 rows m8-15 @k, grp2 rows m0-7 @k+4, grp3 m8-15 @k+4
    const uint32_t aoff = (uint32_t)(((wm + (lane & 15)) * LDK + 4 * (lane >> 4)) * 4);
    // B x4: grp0 rows n0-7 @k, grp1 rows n0-7 @k+4, grp2 rows n8-15 @k, grp3 n8-15 @k+4
    const uint32_t boff = (uint32_t)(((wn + (lane & 7) + 8 * ((lane >> 4) & 1)) * LDK
                                      + 4 * ((lane >> 3) & 1)) * 4);

    int buf = 0;
    for (int kt = 0; kt < ktiles; ++kt) {
        if (kt + 1 < ktiles) load_tile(kt + 1, buf ^ 1);
        cp_commit();
        cp_wait<1>();
        __syncthreads();

        const uint32_t sb  = smb + (uint32_t)(buf * STAGE * 4);
        const uint32_t aH  = sb + aoff;
        const uint32_t bH  = sb + TILE_F * 4 + boff;
        const uint32_t aL  = sb + 2 * TILE_F * 4 + aoff;
        const uint32_t bL  = sb + 3 * TILE_F * 4 + boff;

#pragma unroll
        for (int ks = 0; ks < 2; ++ks) {
            const uint32_t ko = ks * 32;           // 8 floats
            uint32_t AH[2][4], AL[2][4];
#pragma unroll
            for (int mf = 0; mf < 2; ++mf) {
                ldsm4(aH + mf * (16 * LDK * 4) + ko, AH[mf]);
                if (CVTA) {
#pragma unroll
                    for (int r = 0; r < 4; ++r)
                        AH[mf][r] = f2tf32(__uint_as_float(AH[mf][r]));
                }
                if (SPLIT) ldsm4(aL + mf * (16 * LDK * 4) + ko, AL[mf]);
            }
#pragma unroll
            for (int p = 0; p < 4; ++p) {
                uint32_t BH[4], BL[4];
                ldsm4(bH + p * (16 * LDK * 4) + ko, BH);   // r0=b0e r1=b1e r2=b0o r3=b1o
                if (SPLIT) ldsm4(bL + p * (16 * LDK * 4) + ko, BL);
#pragma unroll
                for (int mf = 0; mf < 2; ++mf) {
                    float* ce = acc[mf][2 * p];
                    float* co = acc[mf][2 * p + 1];
                    if (SPLIT) {
                        mma8(ce, AH[mf][0], AH[mf][1], AH[mf][2], AH[mf][3], BL[0], BL[1]);
                        mma8(ce, AL[mf][0], AL[mf][1], AL[mf][2], AL[mf][3], BH[0], BH[1]);
                        mma8(co, AH[mf][0], AH[mf][1], AH[mf][2], AH[mf][3], BL[2], BL[3]);
                        mma8(co, AL[mf][0], AL[mf][1], AL[mf][2], AL[mf][3], BH[2], BH[3]);
                    }
                    mma8(ce, AH[mf][0], AH[mf][1], AH[mf][2], AH[mf][3], BH[0], BH[1]);
                    mma8(co, AH[mf][0], AH[mf][1], AH[mf][2], AH[mf][3], BH[2], BH[3]);
                }
            }
        }
        __syncthreads();
        buf ^= 1;
    }

    // ---- epilogue ----
#pragma unroll
    for (int mf = 0; mf < 2; ++mf) {
#pragma unroll
        for (int nf = 0; nf < 8; ++nf) {
            const int r0 = m0 + wm + mf * 16 + g;
            const int r1 = r0 + 8;
            const int cb = n0 + wn + nf * 8 + 2 * tg;
#pragma unroll
            for (int h = 0; h < 2; ++h) {        // h: 0 -> (r0), 1 -> (r1)
                int gm = h ? r1 : r0;
                if (gm >= M) continue;
#pragma unroll
                for (int q = 0; q < 2; ++q) {    // q: col cb+q
                    int gn = cb + q;
                    if (gn >= N) continue;
                    float v = acc[mf][nf][h * 2 + q];
                    long long off = (long long)gm * c_m + (long long)gn * c_n;
                    if (EPI == 0) {
                        v *= scale;
                        if (bias) v += bias[gn];
                        C[off] = v;
                    } else if (EPI == 1) {
                        float hi = tf32f(v);
                        C[off]  = hi;
                        C2[off] = tf32f(v - hi);
                    } else {
                        C[off] = tf32f(v);
                    }
                }
            }
        }
    }
}

// Dynamic smem sizes (bytes)
constexpr int SMEM_SPLIT  = 2 * 4 * TILE_F * 4;   // 81920
constexpr int SMEM_SINGLE = 2 * 2 * TILE_F * 4;   // 40960

// ---------------------------------------------------------------------------
// Prep 1: transpose + tf32-split x: [b][E][S] -> g_xh/g_xl [b][s][e]
// ---------------------------------------------------------------------------
__global__ void prep_x_kernel(const float* __restrict__ x)
{
    __shared__ float t[32][33];
    const int b  = blockIdx.z;
    const int s0 = blockIdx.x * 32;
    const int e0 = blockIdx.y * 32;
    const int tx = threadIdx.x, ty = threadIdx.y;
#pragma unroll
    for (int j = 0; j < 4; ++j) {
        int e = e0 + ty + j * 8, s = s0 + tx;
        if (e < E_ && s < S_) t[ty + j * 8][tx] = x[((long long)b * E_ + e) * S_ + s];
    }
    __syncthreads();
#pragma unroll
    for (int j = 0; j < 4; ++j) {
        int s = s0 + ty + j * 8, e = e0 + tx;
        if (s < S_ && e < E_) {
            float v = t[tx][ty + j * 8];
            float hi = tf32f(v);
            long long o = ((long long)b * S_ + s) * E_ + e;
            g_xh[o] = hi;
            g_xl[o] = tf32f(v - hi);
        }
    }
}

// ---------------------------------------------------------------------------
// Prep 2: transpose + tf32-split Q/K/V: [h][e][f] -> [p][h][f][e]
// ---------------------------------------------------------------------------
__global__ void prep_qkv_kernel(const float* __restrict__ Qm,
                                const float* __restrict__ Km,
                                const float* __restrict__ Vm)
{
    __shared__ float t[32][33];
    const int z = blockIdx.z;          // p*H + h
    const int p = z / H_, h = z % H_;
    const float* src = (p == 0 ? Qm : (p == 1 ? Km : Vm)) + (long long)h * E_ * E_;
    const int f0 = blockIdx.x * 32;
    const int e0 = blockIdx.y * 32;
    const int tx = threadIdx.x, ty = threadIdx.y;
#pragma unroll
    for (int j = 0; j < 4; ++j) {
        int e = e0 + ty + j * 8, f = f0 + tx;
        t[ty + j * 8][tx] = src[e * E_ + f];
    }
    __syncthreads();
#pragma unroll
    for (int j = 0; j < 4; ++j) {
        int f = f0 + ty + j * 8, e = e0 + tx;
        float v = t[tx][ty + j * 8];
        float hi = tf32f(v);
        long long o = ((long long)z * E_ + f) * E_ + e;
        g_pth[o] = hi;
        g_ptl[o] = tf32f(v - hi);
    }
}

// ---------------------------------------------------------------------------
// Prep 3: round W to tf32; zero g_v pad columns (t = S_..SP_-1)
// ---------------------------------------------------------------------------
__global__ void prep_w_kernel(const float* __restrict__ W)
{
    int i = blockIdx.x * 256 + threadIdx.x;
    if (i < E_ * HE_) g_wh[i] = tf32f(W[i]);
    if (i < B_ * H_ * E_ * (SP_ - S_)) {
        int j   = i % (SP_ - S_);
        int bf  = i / (SP_ - S_);
        g_v[(long long)bf * SP_ + S_ + j] = 0.0f;
    }
}

// ---------------------------------------------------------------------------
// Stage 1: qkv. A=g_xh/l [s][e], B=g_pth/l [f][e]. q,k -> hi/lo; v -> [f][t] tf32.
// ---------------------------------------------------------------------------
__global__ __launch_bounds__(256, 2) void qkv_kernel()
{
    const int z  = blockIdx.z;
    const int p  = z / (B_ * H_);
    const int bh = z % (B_ * H_);
    const int b  = bh / H_;
    const int h  = bh % H_;
    const float* Ah = g_xh + (long long)b * S_ * E_;
    const float* Al = g_xl + (long long)b * S_ * E_;
    const float* Bh = g_pth + (long long)(p * H_ + h) * E_ * E_;
    const float* Bl = g_ptl + (long long)(p * H_ + h) * E_ * E_;
    if (p < 2) {
        float* C  = (p == 0 ? g_qh : g_kh) + (long long)bh * S_ * E_;
        float* C2 = (p == 0 ? g_ql : g_kl) + (long long)bh * S_ * E_;
        mma_gemm<true, true, true, false, 1>(
            Ah, Al, E_, E_, Bh, Bl, E_, E_,
            C, C2, E_, 1, S_, E_, E_, 1.0f, nullptr);
    } else {
        float* C = g_v + (long long)bh * E_ * SP_;     // element (s, f) at [f][s]
        mma_gemm<true, true, true, false, 2>(
            Ah, Al, E_, E_, Bh, Bl, E_, E_,
            C, nullptr, 1, SP_, S_, E_, E_, 1.0f, nullptr);
    }
}

// ---------------------------------------------------------------------------
// Stage 2: scores -> atten region (raw logits * 1/sqrt(E)). Pure LDSM+HMMA.
// ---------------------------------------------------------------------------
__global__ __launch_bounds__(256, 2) void scores_kernel(float* __restrict__ att)
{
    const int bh = blockIdx.z;
    const long long qo = (long long)bh * S_ * E_;
    float* C = att + (long long)bh * S_ * S_;
    mma_gemm<true, true, true, false, 0>(
        g_qh + qo, g_ql + qo, E_, E_,
        g_kh + qo, g_kl + qo, E_, E_,
        C, nullptr, S_, 1, S_, S_, E_, 0.08838834764831845f, nullptr);
}

// ---------------------------------------------------------------------------
// Stage 3: in-place row softmax over length S=1025. One 256-thread block/row.
// ---------------------------------------------------------------------------
__global__ __launch_bounds__(256) void softmax_kernel(float* __restrict__ att)
{
    const long long row = blockIdx.x;
    float* p = att + row * (long long)S_;
    const int tid = threadIdx.x;

    float v[5];
    float mx = -3.4e38f;
#pragma unroll
    for (int i = 0; i < 5; ++i) {
        int idx = tid + i * 256;
        v[i] = (idx < S_) ? p[idx] : -3.4e38f;
        mx = fmaxf(mx, v[i]);
    }
    __shared__ float redm[8];
    __shared__ float reds[8];
#pragma unroll
    for (int o = 16; o > 0; o >>= 1) mx = fmaxf(mx, __shfl_xor_sync(0xffffffffu, mx, o));
    if ((tid & 31) == 0) redm[tid >> 5] = mx;
    __syncthreads();
    mx = redm[0];
#pragma unroll
    for (int w = 1; w < 8; ++w) mx = fmaxf(mx, redm[w]);

    float sum = 0.0f;
#pragma unroll
    for (int i = 0; i < 5; ++i) {
        int idx = tid + i * 256;
        if (idx < S_) { v[i] = __expf(v[i] - mx); sum += v[i]; }
        else v[i] = 0.0f;
    }
#pragma unroll
    for (int o = 16; o > 0; o >>= 1) sum += __shfl_xor_sync(0xffffffffu, sum, o);
    if ((tid & 31) == 0) reds[tid >> 5] = sum;
    __syncthreads();
    sum = reds[0];
#pragma unroll
    for (int w = 1; w < 8; ++w) sum += reds[w];
    const float inv = __frcp_rn(sum);

#pragma unroll
    for (int i = 0; i < 5; ++i) {
        int idx = tid + i * 256;
        if (idx < S_) p[idx] = v[i] * inv;
    }
}

// ---------------------------------------------------------------------------
// Stage 4: av. A=atten [s][t] (cvt in regs), B=g_v [f][t] (pre-rounded).
// o written tf32-rounded (feeds proj which is single-tf32 anyway).
// ---------------------------------------------------------------------------
__global__ __launch_bounds__(256, 2) void av_kernel(const float* __restrict__ att)
{
    const int bh = blockIdx.z;
    const int b = bh / H_;
    const int h = bh % H_;
    const float* A = att + (long long)bh * S_ * S_;
    const float* Bv = g_v + (long long)bh * E_ * SP_;
    float* C = g_o + (long long)b * S_ * HE_ + (long long)h * E_;
    mma_gemm<false, false, true, true, 2>(
        A, nullptr, S_, S_,
        Bv, nullptr, SP_, SP_,
        C, nullptr, HE_, 1, S_, E_, S_, 1.0f, nullptr);
}

// ---------------------------------------------------------------------------
// Stage 5: proj. A=g_o [s][k] (pre-rounded), B=g_wh [e][k]. Out transposed.
// ---------------------------------------------------------------------------
__global__ __launch_bounds__(256, 2) void proj_kernel(
    const float* __restrict__ bias, float* __restrict__ out)
{
    const int b = blockIdx.z;
    const float* A = g_o + (long long)b * S_ * HE_;
    float* C = out + (long long)b * E_ * S_;
    mma_gemm<false, true, true, false, 0>(
        A, nullptr, HE_, HE_,
        g_wh, nullptr, HE_, HE_,
        C, nullptr, 1, S_, S_, E_, HE_, 1.0f, bias);
}

// ---------------------------------------------------------------------------
extern "C" void kernel_launch(void* const* d_in, const int* in_sizes, int n_in,
                              void* d_out, int out_size)
{
    (void)in_sizes; (void)n_in; (void)out_size;
    const float* x    = (const float*)d_in[0];
    const float* Qm   = (const float*)d_in[1];
    const float* Km   = (const float*)d_in[2];
    const float* Vm   = (const float*)d_in[3];
    const float* W    = (const float*)d_in[4];
    const float* bias = (const float*)d_in[5];

    float* out = (float*)d_out;
    float* att = out + (long long)B_ * E_ * S_;   // atten region follows out

    const int MT = (S_ + 127) / 128;  // 9

    static bool attr_done = false;
    if (!attr_done) {
        cudaFuncSetAttribute(qkv_kernel,
            cudaFuncAttributeMaxDynamicSharedMemorySize, SMEM_SPLIT);
        cudaFuncSetAttribute(scores_kernel,
            cudaFuncAttributeMaxDynamicSharedMemorySize, SMEM_SPLIT);
        cudaFuncSetAttribute(av_kernel,
            cudaFuncAttributeMaxDynamicSharedMemorySize, SMEM_SINGLE);
        cudaFuncSetAttribute(proj_kernel,
            cudaFuncAttributeMaxDynamicSharedMemorySize, SMEM_SINGLE);
        attr_done = true;
    }

    prep_x_kernel  <<<dim3((S_ + 31) / 32, E_ / 32, B_), dim3(32, 8)>>>(x);
    prep_qkv_kernel<<<dim3(E_ / 32, E_ / 32, 3 * H_),    dim3(32, 8)>>>(Qm, Km, Vm);
    prep_w_kernel  <<<(E_ * HE_ + 255) / 256, 256>>>(W);

    qkv_kernel    <<<dim3(MT, 1, 3 * B_ * H_), 256, SMEM_SPLIT>>>();
    scores_kernel <<<dim3(MT, MT, B_ * H_),    256, SMEM_SPLIT>>>(att);
    softmax_kernel<<<dim3(B_ * H_ * S_),       256>>>(att);
    av_kernel     <<<dim3(MT, 1, B_ * H_),     256, SMEM_SINGLE>>>(att);
    proj_kernel   <<<dim3(MT, 1, B_),          256, SMEM_SINGLE>>>(bias, out);
}

// round 8
// speedup vs baseline: 1.8755x; 1.4293x over previous
#include <cuda_runtime.h>
#include <cuda_fp16.h>
#include <cstdint>

// Problem dims
constexpr int B_    = 8;
constexpr int H_    = 9;
constexpr int E_    = 128;
constexpr int S_    = 1025;
constexpr int HE_   = H_ * E_;      // 1152
constexpr int SPAD_ = 1032;         // padded S (halfs): 1032*2 bytes, 16B multiple
constexpr long long QKV_ELEMS = (long long)B_ * H_ * S_ * E_;   // 9,446,400

// Scratch (device globals: allocation-free per harness rules) — all fp16
__device__ __half g_xh[(long long)B_ * S_ * E_];      // x^T [b][s][e] hi
__device__ __half g_xl[(long long)B_ * S_ * E_];      // lo
__device__ __half g_pth[3 * H_ * E_ * E_];            // {Q,K,V}^T [p*H+h][f][e] hi
__device__ __half g_ptl[3 * H_ * E_ * E_];            // lo
__device__ __half g_wh[E_ * HE_];                     // W [e][k] single fp16
__device__ __half g_qh[QKV_ELEMS];                    // q [bh][s][e] hi
__device__ __half g_ql[QKV_ELEMS];                    // lo
__device__ __half g_kh[QKV_ELEMS];                    // k hi
__device__ __half g_kl[QKV_ELEMS];                    // lo
__device__ __half g_v [(long long)B_ * H_ * E_ * SPAD_];   // v^T [bh][f][t] fp16
__device__ __half g_ah[(long long)B_ * H_ * S_ * SPAD_];   // atten fp16 copy [bh][s][t]
__device__ __half g_o [(long long)B_ * S_ * HE_];     // o [b][s][h*E+f] fp16

// ---------------------------------------------------------------------------
// async-copy / mma helpers
// ---------------------------------------------------------------------------
__device__ __forceinline__ void cp_async16h(uint32_t dst, const __half* src, bool p) {
    int sz = p ? 16 : 0;   // src-size 0 => 16-byte ZERO-FILL at dst (HW guarantee)
    asm volatile("cp.async.cg.shared.global [%0], [%1], 16, %2;\n"
                 :: "r"(dst), "l"(src), "r"(sz));
}
__device__ __forceinline__ void cp_commit() {
    asm volatile("cp.async.commit_group;\n" ::: "memory");
}
template <int N>
__device__ __forceinline__ void cp_wait() {
    asm volatile("cp.async.wait_group %0;\n" :: "n"(N) : "memory");
}
__device__ __forceinline__ void ldsm4(uint32_t addr, uint32_t r[4]) {
    asm volatile("ldmatrix.sync.aligned.m8n8.x4.shared.b16 {%0,%1,%2,%3}, [%4];"
                 : "=r"(r[0]), "=r"(r[1]), "=r"(r[2]), "=r"(r[3]) : "r"(addr));
}
// fp16 m16n8k16, fp32 accumulate
__device__ __forceinline__ void mma16h(float* c, const uint32_t a[4],
                                       uint32_t b0, uint32_t b1)
{
    asm volatile(
        "mma.sync.aligned.m16n8k16.row.col.f32.f16.f16.f32 "
        "{%0,%1,%2,%3},{%4,%5,%6,%7},{%8,%9},{%0,%1,%2,%3};"
        : "+f"(c[0]), "+f"(c[1]), "+f"(c[2]), "+f"(c[3])
        : "r"(a[0]), "r"(a[1]), "r"(a[2]), "r"(a[3]), "r"(b0), "r"(b1));
}

// ---------------------------------------------------------------------------
// fp16 GEMM core. All operands K-contiguous halfs in gmem: X[outer][k], row
// stride ld (halfs). smem tiles [outer 128][k 32], row stride LDH=40 halfs
// (80B: ldmatrix rows hit 8 distinct bank groups; 16B-aligned rows).
// 256 thr = 8 warps (4m x 2n), warp 32x64, m16n8k16 via ldmatrix.x4.b16.
// SPLIT: hi/lo operand pairs, 3 mma per fragment pair (2xFP16 split).
// EPI: 0 = fp32 C=acc*scale(+bias); 1 = fp16 hi->C, lo->C2; 2 = fp16 C.
// Loads are 8-half cp.async chunks; klim = allocated (padded) row length.
// Out-of-range chunks zero-fill smem (src-size 0), so edge tiles are exact.
// ---------------------------------------------------------------------------
constexpr int LDH    = 40;              // halfs per smem row
constexpr int TILE_B = 128 * LDH * 2;   // 10240 bytes per operand tile

template<bool SPLIT, int EPI>
__device__ __forceinline__ void hgemm(
    const __half* __restrict__ Ah, const __half* __restrict__ Al, long long lda, int kalim,
    const __half* __restrict__ Bh, const __half* __restrict__ Bl, long long ldb, int kblim,
    void* __restrict__ Cv, void* __restrict__ C2v, long long c_m, long long c_n,
    int M, int N, int K, float scale, const float* __restrict__ bias)
{
    constexpr int STG = (SPLIT ? 4 : 2) * TILE_B;    // bytes per stage
    extern __shared__ __half smh[];

    const int tid  = threadIdx.x;
    const int lane = tid & 31;
    const int wid  = tid >> 5;
    const int g    = lane >> 2;
    const int tg   = lane & 3;
    const int wm   = (wid & 3) * 32;
    const int wn   = (wid >> 2) * 64;
    const int m0   = blockIdx.x * 128;
    const int n0   = blockIdx.y * 128;

    const uint32_t smb = (uint32_t)__cvta_generic_to_shared(smh);

    // one operand tile (128 outer x 32 k halfs) -> smem at byte base dst
    auto load_op = [&](const __half* src, long long ld, int klim, int o0,
                       int onum, int k0, uint32_t dst) {
#pragma unroll
        for (int it = 0; it < 2; ++it) {
            int idx = it * 256 + tid;       // 512 chunks of 8 halfs
            int o  = idx >> 2;
            int kh = (idx & 3) * 8;
            int go = o0 + o, gk = k0 + kh;
            bool p = (go < onum) && (gk + 8 <= klim);
            const __half* s = p ? (src + (long long)go * ld + gk) : src;
            cp_async16h(dst + (uint32_t)((o * LDH + kh) * 2), s, p);
        }
    };

    auto load_tile = [&](int kt, int stage) {
        const int k0 = kt * 32;
        const uint32_t sb = smb + (uint32_t)(stage * STG);
        load_op(Ah, lda, kalim, m0, M, k0, sb);
        load_op(Bh, ldb, kblim, n0, N, k0, sb + TILE_B);
        if (SPLIT) {
            load_op(Al, lda, kalim, m0, M, k0, sb + 2 * TILE_B);
            load_op(Bl, ldb, kblim, n0, N, k0, sb + 3 * TILE_B);
        }
    };

    float acc[2][8][4];
#pragma unroll
    for (int i = 0; i < 2; ++i)
#pragma unroll
        for (int j = 0; j < 8; ++j)
#pragma unroll
            for (int r = 0; r < 4; ++r) acc[i][j][r] = 0.0f;

    const int ktiles = (K + 31) / 32;
    load_tile(0, 0);
    cp_commit();

    // ldmatrix per-lane byte offsets within an operand tile.
    // A x4 mats: (m0-7,k0-7),(m8-15,k0-7),(m0-7,k8-15),(m8-15,k8-15)
    const uint32_t aoff = (uint32_t)(
        (wm + (lane & 7) + 8 * ((lane >> 3) & 1)) * LDH * 2 + 16 * (lane >> 4));
    // B x4 mats: (n0-7,k0-7),(n0-7,k8-15),(n8-15,k0-7),(n8-15,k8-15)
    //   -> regs r0,r1 = b0,b1 of even n8-tile; r2,r3 = b0,b1 of odd
    const uint32_t boff = (uint32_t)(
        (wn + (lane & 7) + 8 * ((lane >> 4) & 1)) * LDH * 2 + 16 * ((lane >> 3) & 1));

    int buf = 0;
    for (int kt = 0; kt < ktiles; ++kt) {
        if (kt + 1 < ktiles) load_tile(kt + 1, buf ^ 1);
        cp_commit();
        cp_wait<1>();
        __syncthreads();

        const uint32_t sb = smb + (uint32_t)(buf * STG);
        const uint32_t aH = sb + aoff;
        const uint32_t bH = sb + TILE_B + boff;
        const uint32_t aL = sb + 2 * TILE_B + aoff;
        const uint32_t bL = sb + 3 * TILE_B + boff;

#pragma unroll
        for (int ks = 0; ks < 2; ++ks) {            // two k16 steps per ktile
            const uint32_t ko = ks * 32;            // 16 halfs = 32 bytes
            uint32_t AH[2][4], AL[2][4];
#pragma unroll
            for (int mf = 0; mf < 2; ++mf) {
                ldsm4(aH + mf * (16 * LDH * 2) + ko, AH[mf]);
                if (SPLIT) ldsm4(aL + mf * (16 * LDH * 2) + ko, AL[mf]);
            }
#pragma unroll
            for (int p = 0; p < 4; ++p) {
                uint32_t BH[4], BL[4];
                ldsm4(bH + p * (16 * LDH * 2) + ko, BH);
                if (SPLIT) ldsm4(bL + p * (16 * LDH * 2) + ko, BL);
#pragma unroll
                for (int mf = 0; mf < 2; ++mf) {
                    float* ce = acc[mf][2 * p];
                    float* co = acc[mf][2 * p + 1];
                    if (SPLIT) {
                        mma16h(ce, AH[mf], BL[0], BL[1]);
                        mma16h(ce, AL[mf], BH[0], BH[1]);
                        mma16h(co, AH[mf], BL[2], BL[3]);
                        mma16h(co, AL[mf], BH[2], BH[3]);
                    }
                    mma16h(ce, AH[mf], BH[0], BH[1]);
                    mma16h(co, AH[mf], BH[2], BH[3]);
                }
            }
        }
        __syncthreads();
        buf ^= 1;
    }

    // ---- epilogue ----
#pragma unroll
    for (int mf = 0; mf < 2; ++mf) {
#pragma unroll
        for (int nf = 0; nf < 8; ++nf) {
            const int r0 = m0 + wm + mf * 16 + g;
            const int cb = n0 + wn + nf * 8 + 2 * tg;
#pragma unroll
            for (int h = 0; h < 2; ++h) {
                int gm = h ? (r0 + 8) : r0;
                if (gm >= M) continue;
#pragma unroll
                for (int q = 0; q < 2; ++q) {
                    int gn = cb + q;
                    if (gn >= N) continue;
                    float v = acc[mf][nf][h * 2 + q];
                    long long off = (long long)gm * c_m + (long long)gn * c_n;
                    if (EPI == 0) {
                        v *= scale;
                        if (bias) v += bias[gn];
                        ((float*)Cv)[off] = v;
                    } else if (EPI == 1) {
                        __half hi = __float2half_rn(v);
                        ((__half*)Cv)[off]  = hi;
                        ((__half*)C2v)[off] = __float2half_rn(v - __half2float(hi));
                    } else {
                        ((__half*)Cv)[off] = __float2half_rn(v);
                    }
                }
            }
        }
    }
}

// Dynamic smem sizes (bytes)
constexpr int SMEM_SPLIT  = 2 * 4 * TILE_B;   // 81920
constexpr int SMEM_SINGLE = 2 * 2 * TILE_B;   // 40960

// ---------------------------------------------------------------------------
// Prep 1: transpose + fp16-split x: [b][E][S] -> g_xh/g_xl [b][s][e]
// ---------------------------------------------------------------------------
__global__ void prep_x_kernel(const float* __restrict__ x)
{
    __shared__ float t[32][33];
    const int b  = blockIdx.z;
    const int s0 = blockIdx.x * 32;
    const int e0 = blockIdx.y * 32;
    const int tx = threadIdx.x, ty = threadIdx.y;
#pragma unroll
    for (int j = 0; j < 4; ++j) {
        int e = e0 + ty + j * 8, s = s0 + tx;
        if (e < E_ && s < S_) t[ty + j * 8][tx] = x[((long long)b * E_ + e) * S_ + s];
    }
    __syncthreads();
#pragma unroll
    for (int j = 0; j < 4; ++j) {
        int s = s0 + ty + j * 8, e = e0 + tx;
        if (s < S_ && e < E_) {
            float v = t[tx][ty + j * 8];
            __half hi = __float2half_rn(v);
            long long o = ((long long)b * S_ + s) * E_ + e;
            g_xh[o] = hi;
            g_xl[o] = __float2half_rn(v - __half2float(hi));
        }
    }
}

// ---------------------------------------------------------------------------
// Prep 2: transpose + fp16-split Q/K/V: [h][e][f] -> [p][h][f][e]
// ---------------------------------------------------------------------------
__global__ void prep_qkv_kernel(const float* __restrict__ Qm,
                                const float* __restrict__ Km,
                                const float* __restrict__ Vm)
{
    __shared__ float t[32][33];
    const int z = blockIdx.z;          // p*H + h
    const int p = z / H_, h = z % H_;
    const float* src = (p == 0 ? Qm : (p == 1 ? Km : Vm)) + (long long)h * E_ * E_;
    const int f0 = blockIdx.x * 32;
    const int e0 = blockIdx.y * 32;
    const int tx = threadIdx.x, ty = threadIdx.y;
#pragma unroll
    for (int j = 0; j < 4; ++j) {
        int e = e0 + ty + j * 8, f = f0 + tx;
        t[ty + j * 8][tx] = src[e * E_ + f];
    }
    __syncthreads();
#pragma unroll
    for (int j = 0; j < 4; ++j) {
        int f = f0 + ty + j * 8, e = e0 + tx;
        float v = t[tx][ty + j * 8];
        __half hi = __float2half_rn(v);
        long long o = ((long long)z * E_ + f) * E_ + e;
        g_pth[o] = hi;
        g_ptl[o] = __float2half_rn(v - __half2float(hi));
    }
}

// ---------------------------------------------------------------------------
// Prep 3: W -> fp16; zero g_v pad columns (t in [S_, SPAD_))
// ---------------------------------------------------------------------------
__global__ void prep_w_kernel(const float* __restrict__ W)
{
    int i = blockIdx.x * 256 + threadIdx.x;
    if (i < E_ * HE_) g_wh[i] = __float2half_rn(W[i]);
    if (i < B_ * H_ * E_ * (SPAD_ - S_)) {
        int j  = i % (SPAD_ - S_);
        int bf = i / (SPAD_ - S_);
        g_v[(long long)bf * SPAD_ + S_ + j] = __float2half_rn(0.0f);
    }
}

// ---------------------------------------------------------------------------
// Stage 1: qkv (2xFP16 split). q,k -> fp16 hi/lo; v -> [f][t] fp16.
// ---------------------------------------------------------------------------
__global__ __launch_bounds__(256, 2) void qkv_kernel()
{
    const int z  = blockIdx.z;
    const int p  = z / (B_ * H_);
    const int bh = z % (B_ * H_);
    const int b  = bh / H_;
    const __half* Ah = g_xh + (long long)b * S_ * E_;
    const __half* Al = g_xl + (long long)b * S_ * E_;
    const int h  = bh % H_;
    const __half* Bh = g_pth + (long long)(p * H_ + h) * E_ * E_;
    const __half* Bl = g_ptl + (long long)(p * H_ + h) * E_ * E_;
    if (p < 2) {
        __half* C  = (p == 0 ? g_qh : g_kh) + (long long)bh * S_ * E_;
        __half* C2 = (p == 0 ? g_ql : g_kl) + (long long)bh * S_ * E_;
        hgemm<true, 1>(Ah, Al, E_, E_, Bh, Bl, E_, E_,
                       C, C2, E_, 1, S_, E_, E_, 1.0f, nullptr);
    } else {
        __half* C = g_v + (long long)bh * E_ * SPAD_;   // (s,f) stored at [f][s]
        hgemm<true, 2>(Ah, Al, E_, E_, Bh, Bl, E_, E_,
                       C, nullptr, 1, SPAD_, S_, E_, E_, 1.0f, nullptr);
    }
}

// ---------------------------------------------------------------------------
// Stage 2: scores (2xFP16 split) -> raw logits * 1/sqrt(E) in atten region.
// ---------------------------------------------------------------------------
__global__ __launch_bounds__(256, 2) void scores_kernel(float* __restrict__ att)
{
    const int bh = blockIdx.z;
    const long long qo = (long long)bh * S_ * E_;
    float* C = att + (long long)bh * S_ * S_;
    hgemm<true, 0>(g_qh + qo, g_ql + qo, E_, E_,
                   g_kh + qo, g_kl + qo, E_, E_,
                   C, nullptr, S_, 1, S_, S_, E_, 0.08838834764831845f, nullptr);
}

// ---------------------------------------------------------------------------
// Stage 3: softmax in-place (fp32) + padded fp16 copy for av.
// ---------------------------------------------------------------------------
__global__ __launch_bounds__(256) void softmax_kernel(float* __restrict__ att)
{
    const long long row = blockIdx.x;
    float* p = att + row * (long long)S_;
    __half* ph = g_ah + row * (long long)SPAD_;
    const int tid = threadIdx.x;

    float v[5];
    float mx = -3.4e38f;
#pragma unroll
    for (int i = 0; i < 5; ++i) {
        int idx = tid + i * 256;
        v[i] = (idx < S_) ? p[idx] : -3.4e38f;
        mx = fmaxf(mx, v[i]);
    }
    __shared__ float redm[8];
    __shared__ float reds[8];
#pragma unroll
    for (int o = 16; o > 0; o >>= 1) mx = fmaxf(mx, __shfl_xor_sync(0xffffffffu, mx, o));
    if ((tid & 31) == 0) redm[tid >> 5] = mx;
    __syncthreads();
    mx = redm[0];
#pragma unroll
    for (int w = 1; w < 8; ++w) mx = fmaxf(mx, redm[w]);

    float sum = 0.0f;
#pragma unroll
    for (int i = 0; i < 5; ++i) {
        int idx = tid + i * 256;
        if (idx < S_) { v[i] = __expf(v[i] - mx); sum += v[i]; }
        else v[i] = 0.0f;
    }
#pragma unroll
    for (int o = 16; o > 0; o >>= 1) sum += __shfl_xor_sync(0xffffffffu, sum, o);
    if ((tid & 31) == 0) reds[tid >> 5] = sum;
    __syncthreads();
    sum = reds[0];
#pragma unroll
    for (int w = 1; w < 8; ++w) sum += reds[w];
    const float inv = __frcp_rn(sum);

#pragma unroll
    for (int i = 0; i < 5; ++i) {
        int idx = tid + i * 256;
        if (idx < S_) {
            float a = v[i] * inv;
            p[idx]  = a;
            ph[idx] = __float2half_rn(a);
        }
    }
    if (tid < SPAD_ - S_) ph[S_ + tid] = __float2half_rn(0.0f);
}

// ---------------------------------------------------------------------------
// Stage 4: av (single fp16). A = g_ah [s][t], B = g_v [f][t]. o -> fp16.
// ---------------------------------------------------------------------------
__global__ __launch_bounds__(256, 2) void av_kernel()
{
    const int bh = blockIdx.z;
    const int b = bh / H_;
    const int h = bh % H_;
    const __half* A  = g_ah + (long long)bh * S_ * SPAD_;
    const __half* Bv = g_v  + (long long)bh * E_ * SPAD_;
    __half* C = g_o + (long long)b * S_ * HE_ + (long long)h * E_;
    hgemm<false, 2>(A, nullptr, SPAD_, SPAD_,
                    Bv, nullptr, SPAD_, SPAD_,
                    C, nullptr, HE_, 1, S_, E_, S_, 1.0f, nullptr);
}

// ---------------------------------------------------------------------------
// Stage 5: proj (single fp16). A = g_o [s][k], B = g_wh [e][k]. Out fp32^T.
// ---------------------------------------------------------------------------
__global__ __launch_bounds__(256, 2) void proj_kernel(
    const float* __restrict__ bias, float* __restrict__ out)
{
    const int b = blockIdx.z;
    const __half* A = g_o + (long long)b * S_ * HE_;
    float* C = out + (long long)b * E_ * S_;
    hgemm<false, 0>(A, nullptr, HE_, HE_,
                    g_wh, nullptr, HE_, HE_,
                    C, nullptr, 1, S_, S_, E_, HE_, 1.0f, bias);
}

// ---------------------------------------------------------------------------
extern "C" void kernel_launch(void* const* d_in, const int* in_sizes, int n_in,
                              void* d_out, int out_size)
{
    (void)in_sizes; (void)n_in; (void)out_size;
    const float* x    = (const float*)d_in[0];
    const float* Qm   = (const float*)d_in[1];
    const float* Km   = (const float*)d_in[2];
    const float* Vm   = (const float*)d_in[3];
    const float* W    = (const float*)d_in[4];
    const float* bias = (const float*)d_in[5];

    float* out = (float*)d_out;
    float* att = out + (long long)B_ * E_ * S_;   // atten region follows out

    const int MT = (S_ + 127) / 128;  // 9

    static bool attr_done = false;
    if (!attr_done) {
        cudaFuncSetAttribute(qkv_kernel,
            cudaFuncAttributeMaxDynamicSharedMemorySize, SMEM_SPLIT);
        cudaFuncSetAttribute(scores_kernel,
            cudaFuncAttributeMaxDynamicSharedMemorySize, SMEM_SPLIT);
        cudaFuncSetAttribute(av_kernel,
            cudaFuncAttributeMaxDynamicSharedMemorySize, SMEM_SINGLE);
        cudaFuncSetAttribute(proj_kernel,
            cudaFuncAttributeMaxDynamicSharedMemorySize, SMEM_SINGLE);
        attr_done = true;
    }

    prep_x_kernel  <<<dim3((S_ + 31) / 32, E_ / 32, B_), dim3(32, 8)>>>(x);
    prep_qkv_kernel<<<dim3(E_ / 32, E_ / 32, 3 * H_),    dim3(32, 8)>>>(Qm, Km, Vm);
    prep_w_kernel  <<<(E_ * HE_ + 255) / 256, 256>>>(W);

    qkv_kernel    <<<dim3(MT, 1, 3 * B_ * H_), 256, SMEM_SPLIT>>>();
    scores_kernel <<<dim3(MT, MT, B_ * H_),    256, SMEM_SPLIT>>>(att);
    softmax_kernel<<<dim3(B_ * H_ * S_),       256>>>(att);
    av_kernel     <<<dim3(MT, 1, B_ * H_),     256, SMEM_SINGLE>>>();
    proj_kernel   <<<dim3(MT, 1, B_),          256, SMEM_SINGLE>>>(bias, out);
}